// round 7
// baseline (speedup 1.0000x reference)
#include <cuda_runtime.h>
#include <cuda_fp16.h>
#include <cstdint>

// Problem constants (fixed shapes per reference)
#define P_POINTS   1500000
#define TOTAL_BEV  40000
#define N_FEAT     4224        // feature rows
#define NCH        80
#define NCH4       20          // 80 channels as 20 x (4 ch)
#define BATCH      32          // points staged per warp iteration
#define WPB        8           // warps per block (256 threads)

// Scratch (no cudaMalloc allowed)
__device__ int   g_seg[TOTAL_BEV + 1];            // seg[b] = lower_bound(ranks_bev, b)
__device__ uint2 g_feat_h[N_FEAT * NCH4];         // feat as fp16: row = 20 x uint2 (4 halfs each), 160 B/row

// ---------------------------------------------------------------------------
// Dtype detection: index values are < 2^31, so if the buffer is really int64
// the high 32 bits of the first 4 u64 words are all zero.
// ---------------------------------------------------------------------------
__device__ __forceinline__ int detect64(const void* __restrict__ rd) {
    const unsigned long long* u = (const unsigned long long*)rd;
    unsigned long long h = (__ldg(u + 0) >> 32) | (__ldg(u + 1) >> 32) |
                           (__ldg(u + 2) >> 32) | (__ldg(u + 3) >> 32);
    return h == 0ULL;
}

__device__ __forceinline__ int ld_idx32(const void* __restrict__ p, int i, int is64) {
    if (is64) return (int)__ldg((const long long*)p + i);
    return __ldg((const int*)p + i);
}

// ---------------------------------------------------------------------------
// Kernel 0: convert feat fp32 -> fp16 (row shrinks 320B -> 160B = 2 L2 lines).
// 4224*80 elems as 168960 float2 -> half2.
// ---------------------------------------------------------------------------
__global__ void convert_feat_kernel(const float* __restrict__ feat) {
    int i = blockIdx.x * blockDim.x + threadIdx.x;   // over N_FEAT*NCH4*2 half2s
    if (i < N_FEAT * NCH4 * 2) {
        float2 v = __ldg((const float2*)feat + i);
        ((__half2*)g_feat_h)[i] = __float22half2_rn(v);
    }
}

// ---------------------------------------------------------------------------
// Kernel 1: per-bin lower_bound over sorted ranks_bev (interpolation-bracketed).
// ---------------------------------------------------------------------------
__global__ void build_seg_kernel(const void* __restrict__ ranks_bev,
                                 const void* __restrict__ ranks_depth) {
    int b = blockIdx.x * blockDim.x + threadIdx.x;
    if (b > TOTAL_BEV) return;
    const int is64 = detect64(ranks_depth);

    long long guess = (long long)b * P_POINTS / TOTAL_BEV;
    int lo = 0, hi = P_POINTS;
    int w = 2048;
    while (w < P_POINTS) {
        int l = (int)guess - w; if (l < 0) l = 0;
        int h = (int)guess + w; if (h > P_POINTS) h = P_POINTS;
        bool okL = (l == 0)        || (ld_idx32(ranks_bev, l - 1, is64) < b);
        bool okR = (h == P_POINTS) || (ld_idx32(ranks_bev, h,     is64) >= b);
        if (okL && okR) { lo = l; hi = h; break; }
        w <<= 2;
    }
    while (lo < hi) {
        int m = (lo + hi) >> 1;
        if (ld_idx32(ranks_bev, m, is64) < b) lo = m + 1; else hi = m;
    }
    g_seg[b] = lo;
}

// ---------------------------------------------------------------------------
// Kernel 2: one warp per BEV bin; double-buffered smem staging + fp16 feat.
//   Stage: all 32 lanes load (rd, rf) coalesced for point p+lane, gather
//   d = depth[rd], pack (d, rf) -> u64 -> smem (alternate buffer).
//   Consume: per point one LDS.64 broadcast + one 2-line fp16 feat gather;
//   lanes 0..19 each own 4 channels (uint2 = 2 half2), fp32 accumulate.
//   The next batch's stage loads are issued BEFORE consuming the current one,
//   hiding the idx->depth L2 latency chain under the consume loop.
// ---------------------------------------------------------------------------
__global__ void __launch_bounds__(256) bev_pool_kernel(
    const float* __restrict__ depth,       // [498432]
    const void* __restrict__ ranks_depth,  // [P]
    const void* __restrict__ ranks_feat,   // [P]
    float* __restrict__ out)               // [40000, 80]
{
    __shared__ unsigned long long stage[WPB][2][BATCH];

    const int warp = (blockIdx.x * blockDim.x + threadIdx.x) >> 5;
    const int wib  = (threadIdx.x >> 5);
    const int lane = threadIdx.x & 31;
    if (warp >= TOTAL_BEV) return;

    const int is64 = detect64(ranks_depth);
    const int lo = g_seg[warp];
    const int hi = g_seg[warp + 1];

    const int  active = (lane < NCH4);
    const int  c4     = active ? lane : 0;   // idle lanes shadow lane 0's line
    const uint2* __restrict__ fvc = g_feat_h + c4;

    float4 acc = make_float4(0.f, 0.f, 0.f, 0.f);

    if (lo < hi) {
        // prologue: stage batch 0
        unsigned long long packed = 0ULL;
        {
            int n0 = min(BATCH, hi - lo);
            if (lane < n0) {
                int   rd = ld_idx32(ranks_depth, lo + lane, is64);
                int   rf = ld_idx32(ranks_feat,  lo + lane, is64);
                float d  = __ldg(depth + rd);
                packed = ((unsigned long long)__float_as_uint(d) << 32) | (unsigned)rf;
            }
        }

        int buf = 0;
        for (int p = lo; p < hi; p += BATCH, buf ^= 1) {
            const int n = min(BATCH, hi - p);
            stage[wib][buf][lane] = packed;
            __syncwarp();

            // issue next batch's stage loads before consuming (latency overlap)
            const int pn = p + BATCH;
            packed = 0ULL;
            if (pn < hi && lane < hi - pn) {
                int   rd = ld_idx32(ranks_depth, pn + lane, is64);
                int   rf = ld_idx32(ranks_feat,  pn + lane, is64);
                float d  = __ldg(depth + rd);
                packed = ((unsigned long long)__float_as_uint(d) << 32) | (unsigned)rf;
            }

            // consume current batch
            if (n == BATCH) {
#pragma unroll 8
                for (int j = 0; j < BATCH; ++j) {
                    unsigned long long u = stage[wib][buf][j];
                    int   rfj = (int)(unsigned)u;
                    float dj  = __uint_as_float((unsigned)(u >> 32));
                    uint2 q = __ldg(fvc + (size_t)rfj * NCH4);
                    float2 f0 = __half22float2(*(const __half2*)&q.x);
                    float2 f1 = __half22float2(*(const __half2*)&q.y);
                    acc.x = fmaf(f0.x, dj, acc.x); acc.y = fmaf(f0.y, dj, acc.y);
                    acc.z = fmaf(f1.x, dj, acc.z); acc.w = fmaf(f1.y, dj, acc.w);
                }
            } else {
                for (int j = 0; j < n; ++j) {
                    unsigned long long u = stage[wib][buf][j];
                    int   rfj = (int)(unsigned)u;
                    float dj  = __uint_as_float((unsigned)(u >> 32));
                    uint2 q = __ldg(fvc + (size_t)rfj * NCH4);
                    float2 f0 = __half22float2(*(const __half2*)&q.x);
                    float2 f1 = __half22float2(*(const __half2*)&q.y);
                    acc.x = fmaf(f0.x, dj, acc.x); acc.y = fmaf(f0.y, dj, acc.y);
                    acc.z = fmaf(f1.x, dj, acc.z); acc.w = fmaf(f1.y, dj, acc.w);
                }
            }
            // single syncwarp per batch: the distance-2 same-buffer reuse is
            // ordered through the NEXT iteration's syncwarp (consume(i) LDS
            // precedes syncwarp(i+1) precedes STS(i+2) in every lane).
        }
    }

    if (active) {
        ((float4*)out)[(size_t)warp * NCH4 + c4] = acc;  // empty bins write zeros
    }
}

// ---------------------------------------------------------------------------
// Launch: inputs (metadata order) = depth, feat, ranks_depth, ranks_feat,
// ranks_bev, interval_starts, interval_lengths, [total_bev]
// interval_* are unused by the reference (segments come from sorted ranks_bev).
// ---------------------------------------------------------------------------
extern "C" void kernel_launch(void* const* d_in, const int* in_sizes, int n_in,
                              void* d_out, int out_size) {
    const float* depth       = (const float*)d_in[0];
    const float* feat        = (const float*)d_in[1];
    const void*  ranks_depth = (const void*)d_in[2];
    const void*  ranks_feat  = (const void*)d_in[3];
    const void*  ranks_bev   = (const void*)d_in[4];
    float*       out         = (float*)d_out;

    convert_feat_kernel<<<(N_FEAT * NCH4 * 2 + 255) / 256, 256>>>(feat);

    build_seg_kernel<<<(TOTAL_BEV + 1 + 255) / 256, 256>>>(ranks_bev, ranks_depth);

    // one warp per bin: 40000 warps, 8 warps/block -> 5000 blocks
    bev_pool_kernel<<<(TOTAL_BEV * 32 + 255) / 256, 256>>>(
        depth, ranks_depth, ranks_feat, out);
}

// round 8
// speedup vs baseline: 1.5144x; 1.5144x over previous
#include <cuda_runtime.h>
#include <cuda_fp16.h>
#include <cstdint>

// Problem constants (fixed shapes per reference)
#define P_POINTS   1500000
#define TOTAL_BEV  40000
#define N_FEAT     4224        // feature rows
#define NCH        80
#define NCH4       20          // 80 channels as 20 x (4 ch)
#define BATCH      32          // points staged per warp iteration
#define WPB        8           // warps per block (256 threads)

#define CONV_THREADS  (N_FEAT * NCH4)          // 84480: one float4 -> uint2 each
#define CONV_BLOCKS   ((CONV_THREADS + 255) / 256)        // 330
#define SEG_BLOCKS    ((TOTAL_BEV + 1 + 255) / 256)       // 157

// Scratch (no cudaMalloc allowed)
__device__ int   g_seg[TOTAL_BEV + 1];        // seg[b] = lower_bound(ranks_bev, b)
__device__ uint2 g_feat_h[N_FEAT * NCH4];     // feat fp16: row = 20 x uint2 (4 halfs), 160 B/row

// ---------------------------------------------------------------------------
// Dtype detection: index values are < 2^31, so if the buffer is really int64
// the high 32 bits of the first 4 u64 words are all zero.
// ---------------------------------------------------------------------------
__device__ __forceinline__ int detect64(const void* __restrict__ rd) {
    const unsigned long long* u = (const unsigned long long*)rd;
    unsigned long long h = (__ldg(u + 0) >> 32) | (__ldg(u + 1) >> 32) |
                           (__ldg(u + 2) >> 32) | (__ldg(u + 3) >> 32);
    return h == 0ULL;
}

__device__ __forceinline__ int ld_idx32(const void* __restrict__ p, int i, int is64) {
    if (is64) return (int)__ldg((const long long*)p + i);
    return __ldg((const int*)p + i);
}

// ---------------------------------------------------------------------------
// Kernel 1 (fused prep):
//   blocks [0, CONV_BLOCKS)                : feat fp32 -> fp16 (float4 -> uint2)
//   blocks [CONV_BLOCKS, +SEG_BLOCKS)      : per-bin lower_bound over ranks_bev
// Independent work, one launch instead of two.
// ---------------------------------------------------------------------------
__global__ void prep_kernel(const float* __restrict__ feat,
                            const void* __restrict__ ranks_bev,
                            const void* __restrict__ ranks_depth) {
    if (blockIdx.x < CONV_BLOCKS) {
        int i = blockIdx.x * blockDim.x + threadIdx.x;   // over N_FEAT*NCH4 float4s
        if (i < CONV_THREADS) {
            float4 v = __ldg((const float4*)feat + i);
            uint2 q;
            *(__half2*)&q.x = __float22half2_rn(make_float2(v.x, v.y));
            *(__half2*)&q.y = __float22half2_rn(make_float2(v.z, v.w));
            g_feat_h[i] = q;
        }
        return;
    }

    int b = (blockIdx.x - CONV_BLOCKS) * blockDim.x + threadIdx.x;
    if (b > TOTAL_BEV) return;
    const int is64 = detect64(ranks_depth);

    // ranks_bev is sorted-uniform: lower_bound(b) ~ b*P/B, sd <~ 620. Bracket
    // the interpolation guess (w=2048 > 3 sigma), widen on rare miss, then an
    // 11-step binary search.
    long long guess = (long long)b * P_POINTS / TOTAL_BEV;
    int lo = 0, hi = P_POINTS;
    int w = 2048;
    while (w < P_POINTS) {
        int l = (int)guess - w; if (l < 0) l = 0;
        int h = (int)guess + w; if (h > P_POINTS) h = P_POINTS;
        bool okL = (l == 0)        || (ld_idx32(ranks_bev, l - 1, is64) < b);
        bool okR = (h == P_POINTS) || (ld_idx32(ranks_bev, h,     is64) >= b);
        if (okL && okR) { lo = l; hi = h; break; }
        w <<= 2;
    }
    while (lo < hi) {
        int m = (lo + hi) >> 1;
        if (ld_idx32(ranks_bev, m, is64) < b) lo = m + 1; else hi = m;
    }
    g_seg[b] = lo;
}

// ---------------------------------------------------------------------------
// Kernel 2: one warp per BEV bin, smem-packed staging (exact R6 structure),
// fp16 feat table (160 B row = always exactly 2 L2 lines per point).
//   Stage: all 32 lanes load (rd, rf) coalesced for point p+lane, gather
//   d = depth[rd], pack (d, rf) -> u64 -> smem.
//   Consume: one LDS.64 broadcast + one 2-line fp16 feat gather per point;
//   lanes 0..19 each own 4 channels (uint2 = 2 half2), fp32 accumulate.
// ---------------------------------------------------------------------------
__global__ void __launch_bounds__(256) bev_pool_kernel(
    const float* __restrict__ depth,       // [498432]
    const void* __restrict__ ranks_depth,  // [P]
    const void* __restrict__ ranks_feat,   // [P]
    float* __restrict__ out)               // [40000, 80]
{
    __shared__ unsigned long long stage[WPB][BATCH];

    const int warp = (blockIdx.x * blockDim.x + threadIdx.x) >> 5;
    const int wib  = (threadIdx.x >> 5);   // warp in block
    const int lane = threadIdx.x & 31;
    if (warp >= TOTAL_BEV) return;

    const int is64 = detect64(ranks_depth);
    const int lo = g_seg[warp];
    const int hi = g_seg[warp + 1];

    const int  active = (lane < NCH4);
    const int  c4     = active ? lane : 0;   // idle lanes shadow lane 0's line
    const uint2* __restrict__ fvc = g_feat_h + c4;

    float4 acc = make_float4(0.f, 0.f, 0.f, 0.f);

    for (int p = lo; p < hi; p += BATCH) {
        const int n = min(BATCH, hi - p);

        // ---- stage: coalesced idx loads + depth gather, pack to smem ----
        unsigned long long packed = 0ULL;
        if (lane < n) {
            int   rd = ld_idx32(ranks_depth, p + lane, is64);
            int   rf = ld_idx32(ranks_feat,  p + lane, is64);
            float d  = __ldg(depth + rd);
            packed = ((unsigned long long)__float_as_uint(d) << 32) | (unsigned)rf;
        }
        stage[wib][lane] = packed;
        __syncwarp();

        // ---- consume: 1 LDS.64 broadcast + 1 fp16 feat gather per point ----
        if (n == BATCH) {
#pragma unroll 8
            for (int j = 0; j < BATCH; ++j) {
                unsigned long long u = stage[wib][j];
                int   rfj = (int)(unsigned)u;
                float dj  = __uint_as_float((unsigned)(u >> 32));
                uint2 q = __ldg(fvc + (size_t)rfj * NCH4);
                float2 f0 = __half22float2(*(const __half2*)&q.x);
                float2 f1 = __half22float2(*(const __half2*)&q.y);
                acc.x = fmaf(f0.x, dj, acc.x); acc.y = fmaf(f0.y, dj, acc.y);
                acc.z = fmaf(f1.x, dj, acc.z); acc.w = fmaf(f1.y, dj, acc.w);
            }
        } else {
            for (int j = 0; j < n; ++j) {
                unsigned long long u = stage[wib][j];
                int   rfj = (int)(unsigned)u;
                float dj  = __uint_as_float((unsigned)(u >> 32));
                uint2 q = __ldg(fvc + (size_t)rfj * NCH4);
                float2 f0 = __half22float2(*(const __half2*)&q.x);
                float2 f1 = __half22float2(*(const __half2*)&q.y);
                acc.x = fmaf(f0.x, dj, acc.x); acc.y = fmaf(f0.y, dj, acc.y);
                acc.z = fmaf(f1.x, dj, acc.z); acc.w = fmaf(f1.y, dj, acc.w);
            }
        }
        __syncwarp();   // protect stage[] before next overwrite
    }

    if (active) {
        ((float4*)out)[(size_t)warp * NCH4 + c4] = acc;  // empty bins write zeros
    }
}

// ---------------------------------------------------------------------------
// Launch: inputs (metadata order) = depth, feat, ranks_depth, ranks_feat,
// ranks_bev, interval_starts, interval_lengths, [total_bev]
// interval_* are unused by the reference (segments come from sorted ranks_bev).
// ---------------------------------------------------------------------------
extern "C" void kernel_launch(void* const* d_in, const int* in_sizes, int n_in,
                              void* d_out, int out_size) {
    const float* depth       = (const float*)d_in[0];
    const float* feat        = (const float*)d_in[1];
    const void*  ranks_depth = (const void*)d_in[2];
    const void*  ranks_feat  = (const void*)d_in[3];
    const void*  ranks_bev   = (const void*)d_in[4];
    float*       out         = (float*)d_out;

    prep_kernel<<<CONV_BLOCKS + SEG_BLOCKS, 256>>>(feat, ranks_bev, ranks_depth);

    // one warp per bin: 40000 warps, 8 warps/block -> 5000 blocks
    bev_pool_kernel<<<(TOTAL_BEV * 32 + 255) / 256, 256>>>(
        depth, ranks_depth, ranks_feat, out);
}